// round 7
// baseline (speedup 1.0000x reference)
#include <cuda_runtime.h>
#include <math.h>

#define SIZE 1000
#define NPTS 8
#define THREADS 256
#define CHUNK 16                      // float4 stores per thread
#define BLK_F4 (THREADS * CHUNK)      // 4096 float4s per block
#define MAXCAND 64

// ---------------------------------------------------------------------------
// tanh(100000*x) with exact fp32 saturation fast path:
// tanhf(t) rounds to exactly +/-1.0f for |t| >= ~9.02, i.e. |x| >= 1e-4.
// ---------------------------------------------------------------------------
__device__ __forceinline__ float vi_sgn(float x) {
    if (fabsf(x) >= 1e-4f) return copysignf(1.0f, x);
    return tanhf(100000.0f * x);
}

// Exact mask element (pre-transpose i=row, j=col), faithful to the reference.
__device__ __forceinline__ float vi_maskval(float a, float b, int i, int j) {
    float x1 = vi_sgn(a - (float)j);
    float y1 = vi_sgn(b - (float)(i + 1));
    float x3 = vi_sgn(a - (float)(j + 1));
    float y3 = vi_sgn(b - (float)i);
    float m1 = vi_sgn(y1 * x1);
    float m3 = vi_sgn(y3 * x3);
    return (1.0f - m1 * m3) * 0.5f;
}

// Transposed mask with zero padding: mt(p,q) = mask(i=q, j=p)
__device__ __forceinline__ float vi_mt(float a, float b, int p, int q) {
    if (p < 0 || p >= SIZE || q < 0 || q >= SIZE) return 0.0f;
    return vi_maskval(a, b, q, p);
}

// ---------------------------------------------------------------------------
// Single fused kernel.
//   - threads 0..7 build the candidate list (closed form + exact fallback)
//   - thread 0 sets a block-level hit flag (candidate in this block's span?)
//   - non-hit blocks (all but <=8): pure unrolled, block-interleaved float4
//     zero stores -> each warp STG.128 covers 512 contiguous bytes
//   - hit blocks: per-element fmax merge (negligible, <=8 blocks)
// Closed form: with both fractional parts in the saturated band, the output
// is a single 1.0 at out[(jc*1000+ic)*10 + cls] (interior points only).
// ---------------------------------------------------------------------------
__global__ void __launch_bounds__(THREADS) vi_fused_kernel(
        const float* __restrict__ z_pos,
        const int* __restrict__ z_cls,
        float4* __restrict__ out4, int n4) {
    __shared__ int   s_off[MAXCAND];
    __shared__ float s_val[MAXCAND];
    __shared__ int   s_cnt;
    __shared__ int   s_hit;

    if (threadIdx.x == 0) s_cnt = 0;
    __syncthreads();

    if (threadIdx.x < NPTS) {
        int n = threadIdx.x;
        float a = z_pos[2 * n + 0] * 1000.0f;
        float b = z_pos[2 * n + 1] * 1000.0f;
        int   c = z_cls[n];
        int  jc = (int)floorf(a);
        int  ic = (int)floorf(b);
        float fa = a - (float)jc;
        float fb = b - (float)ic;
        bool sat = (fa >= 1e-4f) && (fa <= 1.0f - 1e-4f) &&
                   (fb >= 1e-4f) && (fb <= 1.0f - 1e-4f);
        if (sat) {
            if (jc >= 1 && jc <= SIZE - 2 && ic >= 1 && ic <= SIZE - 2) {
                int k = atomicAdd(&s_cnt, 1);
                s_off[k] = (jc * SIZE + ic) * 10 + c;
                s_val[k] = 1.0f;
            }
        } else {
            // rare near-integer band: exact 7x7 window evaluation
            for (int t = 0; t < 49; t++) {
                int p = jc + (t % 7) - 3;
                int q = ic + (t / 7) - 3;
                if (p < 0 || p >= SIZE || q < 0 || q >= SIZE) continue;
                float conv = vi_mt(a, b, p - 1, q) + vi_mt(a, b, p + 1, q) +
                             vi_mt(a, b, p, q - 1) + vi_mt(a, b, p, q + 1);
                float v = conv - 3.0f;
                if (v > 0.0f) {
                    int k = atomicAdd(&s_cnt, 1);
                    s_off[k] = (p * SIZE + q) * 10 + c;
                    s_val[k] = v;
                }
            }
        }
    }
    __syncthreads();

    int blk_base4 = blockIdx.x * BLK_F4;            // first float4 of this block
    if (threadIdx.x == 0) {
        int e_base = blk_base4 * 4;                 // first element
        int hit = 0, cnt = s_cnt;
        for (int k = 0; k < cnt; k++) {
            unsigned d = (unsigned)(s_off[k] - e_base);
            hit |= (d < (unsigned)(BLK_F4 * 4));
        }
        s_hit = hit;
    }
    __syncthreads();

    const float4 z = make_float4(0.f, 0.f, 0.f, 0.f);

    if (!s_hit) {
        // fast path: block-interleaved -> warp-contiguous 512B stores
        int i = blk_base4 + threadIdx.x;
        #pragma unroll
        for (int u = 0; u < CHUNK; u++) {
            if (i < n4) out4[i] = z;
            i += THREADS;
        }
    } else {
        int cnt = s_cnt;
        int i = blk_base4 + threadIdx.x;
        for (int u = 0; u < CHUNK; u++) {
            if (i < n4) {
                float4 v = z;
                int e = i * 4;
                for (int k = 0; k < cnt; k++) {
                    int d = s_off[k] - e;
                    float val = s_val[k];
                    if (d == 0) v.x = fmaxf(v.x, val);
                    else if (d == 1) v.y = fmaxf(v.y, val);
                    else if (d == 2) v.z = fmaxf(v.z, val);
                    else if (d == 3) v.w = fmaxf(v.w, val);
                }
                out4[i] = v;
            }
            i += THREADS;
        }
    }
}

extern "C" void kernel_launch(void* const* d_in, const int* in_sizes, int n_in,
                              void* d_out, int out_size) {
    const float* z_pos = (const float*)d_in[0];  // [8,2] fp32
    const int*   z_cls = (const int*)d_in[1];    // [8] int32
    float* out = (float*)d_out;                  // [1000,1000,10] fp32

    int n4 = out_size / 4;                       // 2,500,000 float4s
    int blocks = (n4 + BLK_F4 - 1) / BLK_F4;     // 611
    vi_fused_kernel<<<blocks, THREADS>>>(z_pos, z_cls, (float4*)out, n4);
}

// round 8
// speedup vs baseline: 1.7066x; 1.7066x over previous
#include <cuda_runtime.h>
#include <math.h>

#define SIZE 1000
#define NPTS 8
#define THREADS 256
#define CHUNK 4                       // float4 stores per thread
#define BLK_F4 (THREADS * CHUNK)      // 1024 float4s (16 KB) per block
#define MAXCAND 512

// ---------------------------------------------------------------------------
// tanh(100000*x) with exact fp32 saturation fast path:
// tanhf(t) rounds to exactly +/-1.0f for |t| >= ~9.02, i.e. |x| >= 1e-4.
// ---------------------------------------------------------------------------
__device__ __forceinline__ float vi_sgn(float x) {
    if (fabsf(x) >= 1e-4f) return copysignf(1.0f, x);
    return tanhf(100000.0f * x);
}

// Exact mask element (pre-transpose i=row, j=col), faithful to the reference.
__device__ __forceinline__ float vi_maskval(float a, float b, int i, int j) {
    float x1 = vi_sgn(a - (float)j);
    float y1 = vi_sgn(b - (float)(i + 1));
    float x3 = vi_sgn(a - (float)(j + 1));
    float y3 = vi_sgn(b - (float)i);
    float m1 = vi_sgn(y1 * x1);
    float m3 = vi_sgn(y3 * x3);
    return (1.0f - m1 * m3) * 0.5f;
}

// Transposed mask with zero padding: mt(p,q) = mask(i=q, j=p)
__device__ __forceinline__ float vi_mt(float a, float b, int p, int q) {
    if (p < 0 || p >= SIZE || q < 0 || q >= SIZE) return 0.0f;
    return vi_maskval(a, b, q, p);
}

// ---------------------------------------------------------------------------
// Single fused kernel, stores-first structure:
//   1. predicated LDG of inputs into registers (issued early, non-blocking)
//   2. 4 block-interleaved float4 zero stores per thread (no barrier first)
//   3. warp 0 builds the candidate list (closed form + exact 7x7 fallback),
//      overlapped behind the store stream; __syncwarp-only synchronization
//   4. one __syncthreads, then <=8 threads grid-wide atomicMax the candidate
//      into this block's freshly zeroed span (intra-block order via barrier)
// Closed form: with both fractional parts saturated, the whole output is a
// single 1.0 at out[(jc*1000+ic)*10 + cls] per interior point.
// ---------------------------------------------------------------------------
__global__ void __launch_bounds__(THREADS) vi_fused_kernel(
        const float* __restrict__ z_pos,
        const int* __restrict__ z_cls,
        float4* __restrict__ out4, int n4) {
    __shared__ int   s_off[MAXCAND];
    __shared__ float s_val[MAXCAND];
    __shared__ int   s_cnt;

    int tid = threadIdx.x;

    // 1. early, predicated input loads (no dependency until step 3)
    float a = 0.f, b = 0.f;
    int   c = 0;
    if (tid < NPTS) {
        a = z_pos[2 * tid + 0] * 1000.0f;
        b = z_pos[2 * tid + 1] * 1000.0f;
        c = z_cls[tid];
    }
    if (tid == 0) s_cnt = 0;

    // 2. zero stores immediately — the bandwidth-bound bulk of the kernel
    const float4 z = make_float4(0.f, 0.f, 0.f, 0.f);
    int i = blockIdx.x * BLK_F4 + tid;
    #pragma unroll
    for (int u = 0; u < CHUNK; u++) {
        if (i < n4) out4[i] = z;
        i += THREADS;
    }

    // 3. candidate list, warp 0 only (covers threads 0..7 and the s_cnt init)
    if (tid < 32) {
        __syncwarp();                          // s_cnt init visible in-warp
        if (tid < NPTS) {
            int  jc = (int)floorf(a);
            int  ic = (int)floorf(b);
            float fa = a - (float)jc;
            float fb = b - (float)ic;
            bool sat = (fa >= 1e-4f) && (fa <= 1.0f - 1e-4f) &&
                       (fb >= 1e-4f) && (fb <= 1.0f - 1e-4f);
            if (sat) {
                if (jc >= 1 && jc <= SIZE - 2 && ic >= 1 && ic <= SIZE - 2) {
                    int k = atomicAdd(&s_cnt, 1);
                    s_off[k] = (jc * SIZE + ic) * 10 + c;
                    s_val[k] = 1.0f;
                }
            } else {
                // rare near-integer band: exact 7x7 window evaluation
                for (int t = 0; t < 49; t++) {
                    int p = jc + (t % 7) - 3;
                    int q = ic + (t / 7) - 3;
                    if (p < 0 || p >= SIZE || q < 0 || q >= SIZE) continue;
                    float conv = vi_mt(a, b, p - 1, q) + vi_mt(a, b, p + 1, q) +
                                 vi_mt(a, b, p, q - 1) + vi_mt(a, b, p, q + 1);
                    float v = conv - 3.0f;
                    if (v > 0.0f) {
                        int k = atomicAdd(&s_cnt, 1);
                        s_off[k] = (p * SIZE + q) * 10 + c;
                        s_val[k] = v;
                    }
                }
            }
        }
        __syncwarp();
    }

    // 4. fix-up after all zero stores in this block have been issued
    __syncthreads();
    int cnt = s_cnt;
    int e_base = blockIdx.x * (BLK_F4 * 4);
    float* out = (float*)out4;
    for (int k = tid; k < cnt; k += THREADS) {
        unsigned d = (unsigned)(s_off[k] - e_base);
        if (d < (unsigned)(BLK_F4 * 4)) {
            atomicMax((int*)&out[s_off[k]], __float_as_int(s_val[k]));
        }
    }
}

extern "C" void kernel_launch(void* const* d_in, const int* in_sizes, int n_in,
                              void* d_out, int out_size) {
    const float* z_pos = (const float*)d_in[0];  // [8,2] fp32
    const int*   z_cls = (const int*)d_in[1];    // [8] int32
    float* out = (float*)d_out;                  // [1000,1000,10] fp32

    int n4 = out_size / 4;                       // 2,500,000 float4s
    int blocks = (n4 + BLK_F4 - 1) / BLK_F4;     // 2442
    vi_fused_kernel<<<blocks, THREADS>>>(z_pos, z_cls, (float4*)out, n4);
}

// round 9
// speedup vs baseline: 1.7881x; 1.0478x over previous
#include <cuda_runtime.h>
#include <math.h>
#include <stdint.h>

#define SIZE 1000
#define NPTS 8
#define THREADS 256
#define SBUF 32768                    // SMEM zero-buffer bytes
#define TOTAL_BYTES 40000000          // 1000*1000*10 fp32
#define BLOCKS 592                    // 4 per SM, exactly 1 wave on 148 SMs
#define CH 67568                      // ceil(TOTAL/BLOCKS) rounded to 16B
#define MAXCAND 400

// ---------------------------------------------------------------------------
// tanh(100000*x) with exact fp32 saturation fast path:
// tanhf(t) rounds to exactly +/-1.0f for |t| >= ~9.02, i.e. |x| >= 1e-4.
// ---------------------------------------------------------------------------
__device__ __forceinline__ float vi_sgn(float x) {
    if (fabsf(x) >= 1e-4f) return copysignf(1.0f, x);
    return tanhf(100000.0f * x);
}

// Exact mask element (pre-transpose i=row, j=col), faithful to the reference.
__device__ __forceinline__ float vi_maskval(float a, float b, int i, int j) {
    float x1 = vi_sgn(a - (float)j);
    float y1 = vi_sgn(b - (float)(i + 1));
    float x3 = vi_sgn(a - (float)(j + 1));
    float y3 = vi_sgn(b - (float)i);
    float m1 = vi_sgn(y1 * x1);
    float m3 = vi_sgn(y3 * x3);
    return (1.0f - m1 * m3) * 0.5f;
}

// Transposed mask with zero padding: mt(p,q) = mask(i=q, j=p)
__device__ __forceinline__ float vi_mt(float a, float b, int p, int q) {
    if (p < 0 || p >= SIZE || q < 0 || q >= SIZE) return 0.0f;
    return vi_maskval(a, b, q, p);
}

// ---------------------------------------------------------------------------
// Single fused kernel, TMA-store structure:
//   1. all threads zero a 32KB SMEM buffer (STS.128, cheap)
//   2. warp 0 builds the candidate list in parallel (closed form + exact
//      7x7 tanhf fallback for the near-integer band)
//   3. __syncthreads (SMEM-only ordering) + fence.proxy.async
//   4. thread 0 issues cp.async.bulk shared->global for its ~66KB output
//      range (3 chunks), commit, wait_group 0
//   5. thread 0 applies candidate atomicMax fix-ups inside its range —
//      ordering vs the zero-fill guaranteed by wait_group 0
// Closed form: with both fractional parts saturated, the whole output is a
// single 1.0 at out[(jc*1000+ic)*10 + cls] per interior point.
// ---------------------------------------------------------------------------
__global__ void __launch_bounds__(THREADS) vi_tma_kernel(
        const float* __restrict__ z_pos,
        const int* __restrict__ z_cls,
        float* __restrict__ out) {
    __shared__ __align__(128) float4 buf[SBUF / 16];
    __shared__ int   s_off[MAXCAND];
    __shared__ float s_val[MAXCAND];
    __shared__ int   s_cnt;

    int tid = threadIdx.x;

    // early, predicated input loads (consumed only by warp 0 below)
    float a = 0.f, b = 0.f;
    int   c = 0;
    if (tid < NPTS) {
        a = z_pos[2 * tid + 0] * 1000.0f;
        b = z_pos[2 * tid + 1] * 1000.0f;
        c = z_cls[tid];
    }
    if (tid == 0) s_cnt = 0;

    // 1. zero the SMEM staging buffer
    const float4 z = make_float4(0.f, 0.f, 0.f, 0.f);
    #pragma unroll
    for (int u = 0; u < SBUF / 16 / THREADS; u++)     // 8 iters
        buf[u * THREADS + tid] = z;

    // 2. candidate list (warp 0 only)
    if (tid < 32) {
        __syncwarp();                                  // s_cnt init visible
        if (tid < NPTS) {
            int  jc = (int)floorf(a);
            int  ic = (int)floorf(b);
            float fa = a - (float)jc;
            float fb = b - (float)ic;
            bool sat = (fa >= 1e-4f) && (fa <= 1.0f - 1e-4f) &&
                       (fb >= 1e-4f) && (fb <= 1.0f - 1e-4f);
            if (sat) {
                if (jc >= 1 && jc <= SIZE - 2 && ic >= 1 && ic <= SIZE - 2) {
                    int k = atomicAdd(&s_cnt, 1);
                    s_off[k] = (jc * SIZE + ic) * 10 + c;
                    s_val[k] = 1.0f;
                }
            } else {
                // rare near-integer band: exact 7x7 window evaluation
                for (int t = 0; t < 49; t++) {
                    int p = jc + (t % 7) - 3;
                    int q = ic + (t / 7) - 3;
                    if (p < 0 || p >= SIZE || q < 0 || q >= SIZE) continue;
                    float conv = vi_mt(a, b, p - 1, q) + vi_mt(a, b, p + 1, q) +
                                 vi_mt(a, b, p, q - 1) + vi_mt(a, b, p, q + 1);
                    float v = conv - 3.0f;
                    if (v > 0.0f) {
                        int k = atomicAdd(&s_cnt, 1);
                        s_off[k] = (p * SIZE + q) * 10 + c;
                        s_val[k] = v;
                    }
                }
            }
        }
        __syncwarp();
    }

    // 3. SMEM writes ordered for everyone, then made visible to async proxy
    __syncthreads();
    asm volatile("fence.proxy.async.shared::cta;" ::: "memory");

    // 4+5. thread 0 streams the block's byte range out via TMA bulk stores
    if (tid == 0) {
        int begin = blockIdx.x * CH;
        int end   = min(begin + CH, TOTAL_BYTES);
        char* gbase = (char*)out;
        uint32_t saddr = (uint32_t)__cvta_generic_to_shared(buf);

        for (int off = begin; off < end; off += SBUF) {
            int sz = min(SBUF, end - off);
            asm volatile(
                "cp.async.bulk.global.shared::cta.bulk_group [%0], [%1], %2;"
                :: "l"(gbase + off), "r"(saddr), "r"(sz) : "memory");
        }
        asm volatile("cp.async.bulk.commit_group;" ::: "memory");
        asm volatile("cp.async.bulk.wait_group 0;" ::: "memory");

        // fix-up: zeros for this range are now visible
        int cnt = s_cnt;
        for (int k = 0; k < cnt; k++) {
            int boff = s_off[k] * 4;
            if (boff >= begin && boff < end)
                atomicMax((int*)&out[s_off[k]], __float_as_int(s_val[k]));
        }
    }
}

extern "C" void kernel_launch(void* const* d_in, const int* in_sizes, int n_in,
                              void* d_out, int out_size) {
    const float* z_pos = (const float*)d_in[0];  // [8,2] fp32
    const int*   z_cls = (const int*)d_in[1];    // [8] int32
    float* out = (float*)d_out;                  // [1000,1000,10] fp32
    (void)in_sizes; (void)n_in; (void)out_size;

    vi_tma_kernel<<<BLOCKS, THREADS>>>(z_pos, z_cls, out);
}

// round 10
// speedup vs baseline: 1.8431x; 1.0308x over previous
#include <cuda_runtime.h>
#include <math.h>
#include <stdint.h>

#define SIZE 1000
#define NPTS 8
#define THREADS 256
#define CHUNK 4                       // float4 stores per thread
#define BLK_F4 (THREADS * CHUNK)      // 1024 float4s (16 KB) per block
#define MAXCAND 400

// ---------------------------------------------------------------------------
// tanh(100000*x) with exact fp32 saturation fast path:
// tanhf(t) rounds to exactly +/-1.0f for |t| >= ~9.02, i.e. |x| >= 1e-4.
// ---------------------------------------------------------------------------
__device__ __forceinline__ float vi_sgn(float x) {
    if (fabsf(x) >= 1e-4f) return copysignf(1.0f, x);
    return tanhf(100000.0f * x);
}

// Exact mask element (pre-transpose i=row, j=col), faithful to the reference.
__device__ __forceinline__ float vi_maskval(float a, float b, int i, int j) {
    float x1 = vi_sgn(a - (float)j);
    float y1 = vi_sgn(b - (float)(i + 1));
    float x3 = vi_sgn(a - (float)(j + 1));
    float y3 = vi_sgn(b - (float)i);
    float m1 = vi_sgn(y1 * x1);
    float m3 = vi_sgn(y3 * x3);
    return (1.0f - m1 * m3) * 0.5f;
}

// Transposed mask with zero padding: mt(p,q) = mask(i=q, j=p)
__device__ __forceinline__ float vi_mt(float a, float b, int p, int q) {
    if (p < 0 || p >= SIZE || q < 0 || q >= SIZE) return 0.0f;
    return vi_maskval(a, b, q, p);
}

// ---------------------------------------------------------------------------
// Fused fill, barrier-free fast path.
//   - 4 block-interleaved float4 zero stores per thread, issued first
//   - every warp's lanes 0..7 compute the 8 closed-form candidate offsets
//     (single 1.0 at (jc*1000+ic)*10+cls per interior, saturated point)
//   - ballot: does any candidate fall in this block's 16KB span? almost
//     always no -> warp done. If yes, the owning thread (same thread that
//     zero-stored that float4) atomicMaxes the value: same-thread same-
//     address ordering, no barrier needed.
//   - non-saturated inputs (near-integer band): block-uniform slow path
//     with exact 7x7 evaluation, shared list and __syncthreads.
// ---------------------------------------------------------------------------
__global__ void __launch_bounds__(THREADS) vi_fused_kernel(
        const float* __restrict__ z_pos,
        const int* __restrict__ z_cls,
        float4* __restrict__ out4, int n4) {
    __shared__ int   s_off[MAXCAND];
    __shared__ float s_val[MAXCAND];
    __shared__ int   s_cnt;

    int tid  = threadIdx.x;
    int lane = tid & 31;

    // early predicated input loads (every warp; broadcast addresses, L2-hit)
    float a = 0.f, b = 0.f;
    int   c = 0;
    if (lane < NPTS) {
        float2 zp = ((const float2*)z_pos)[lane];
        a = zp.x * 1000.0f;
        b = zp.y * 1000.0f;
        c = z_cls[lane];
    }

    // 1. zero stores first — the bandwidth-bound bulk, no dependencies
    const float4 z = make_float4(0.f, 0.f, 0.f, 0.f);
    int blk_f4 = blockIdx.x * BLK_F4;
    {
        int i = blk_f4 + tid;
        #pragma unroll
        for (int u = 0; u < CHUNK; u++) {
            if (i < n4) out4[i] = z;
            i += THREADS;
        }
    }

    // 2. closed-form candidate per lane (overlaps store drain)
    int  off = -1;
    bool sat = true;
    if (lane < NPTS) {
        int  jc = (int)floorf(a);
        int  ic = (int)floorf(b);
        float fa = a - (float)jc;
        float fb = b - (float)ic;
        sat = (fa >= 1e-4f) && (fa <= 1.0f - 1e-4f) &&
              (fb >= 1e-4f) && (fb <= 1.0f - 1e-4f);
        if (sat && jc >= 1 && jc <= SIZE - 2 && ic >= 1 && ic <= SIZE - 2)
            off = (jc * SIZE + ic) * 10 + c;
    }

    unsigned bad = __ballot_sync(0xffffffffu, (lane < NPTS) && !sat);

    if (bad == 0) {
        // 3. fast path: block-uniform, barrier-free
        int blk_lo = blk_f4 * 4;                  // first element of block
        bool inblk = (off >= blk_lo) && (off < blk_lo + BLK_F4 * 4);
        unsigned m = __ballot_sync(0xffffffffu, inblk);
        while (m) {
            int n = __ffs(m) - 1;
            m &= m - 1;
            int o = __shfl_sync(0xffffffffu, off, n);
            int r = (o >> 2) - blk_f4;            // float4 index within block
            if ((r & (THREADS - 1)) == tid) {     // I zero-stored this float4
                atomicMax((int*)((float*)out4 + o), __float_as_int(1.0f));
            }
        }
    } else {
        // 4. slow path (rare near-integer band): exact 7x7, shared list
        if (tid == 0) s_cnt = 0;
        __syncthreads();
        if (tid < NPTS) {
            int jc = (int)floorf(a);
            int ic = (int)floorf(b);
            for (int t = 0; t < 49; t++) {
                int p = jc + (t % 7) - 3;
                int q = ic + (t / 7) - 3;
                if (p < 0 || p >= SIZE || q < 0 || q >= SIZE) continue;
                float conv = vi_mt(a, b, p - 1, q) + vi_mt(a, b, p + 1, q) +
                             vi_mt(a, b, p, q - 1) + vi_mt(a, b, p, q + 1);
                float v = conv - 3.0f;
                if (v > 0.0f) {
                    int k = atomicAdd(&s_cnt, 1);
                    s_off[k] = (p * SIZE + q) * 10 + c;
                    s_val[k] = v;
                }
            }
        }
        __syncthreads();   // also makes all block zero-stores visible
        int cnt = s_cnt;
        int e_lo = blk_f4 * 4;
        for (int k = tid; k < cnt; k += THREADS) {
            unsigned d = (unsigned)(s_off[k] - e_lo);
            if (d < (unsigned)(BLK_F4 * 4))
                atomicMax((int*)((float*)out4 + s_off[k]),
                          __float_as_int(s_val[k]));
        }
    }
}

extern "C" void kernel_launch(void* const* d_in, const int* in_sizes, int n_in,
                              void* d_out, int out_size) {
    const float* z_pos = (const float*)d_in[0];  // [8,2] fp32
    const int*   z_cls = (const int*)d_in[1];    // [8] int32
    float* out = (float*)d_out;                  // [1000,1000,10] fp32

    int n4 = out_size / 4;                       // 2,500,000 float4s
    int blocks = (n4 + BLK_F4 - 1) / BLK_F4;     // 2442
    vi_fused_kernel<<<blocks, THREADS>>>(z_pos, z_cls, (float4*)out, n4);
}